// round 2
// baseline (speedup 1.0000x reference)
#include <cuda_runtime.h>
#include <cuda_bf16.h>

// PathRaster2d: quadratic Bezier (3 cps) on 2048x2048.
// R2: 128x32 tiles (1024 blocks), 4x float4 stores/thread, single barrier,
// ballot-compacted near-sample list (exact pruning: dist(p,s) >= boxdist(s),
// so samples with boxdist >= LINE_WIDTH can never decide a nonzero pixel).

#define CANVAS_H 2048
#define CANVAS_W 2048
#define NSAMP 32
#define TILE_W 128
#define TILE_H 32

__global__ void __launch_bounds__(256)
path_raster_kernel(const float* __restrict__ kp, float* __restrict__ out)
{
    __shared__ float csy[NSAMP];
    __shared__ float csx[NSAMP];
    __shared__ int s_count;

    const int tx = threadIdx.x;          // 0..31
    const int ty = threadIdx.y;          // 0..7
    const int x0 = blockIdx.x * TILE_W;
    const int y0 = blockIdx.y * TILE_H;

    if (ty == 0) {                       // warp 0: compute + compact samples
        // t_i = i * fl(1/31), endpoint forced to 1.0 (matches jnp.linspace)
        float t = (tx == NSAMP - 1) ? 1.0f : (float)tx * (1.0f / (float)(NSAMP - 1));
        float u = __fsub_rn(1.0f, t);
        float b0 = __fmul_rn(u, u);
        float b1 = __fmul_rn(__fmul_rn(2.0f, t), u);
        float b2 = __fmul_rn(t, t);
        float ky0 = __fmul_rn(kp[0], 2048.0f), kx0 = __fmul_rn(kp[1], 2048.0f);
        float ky1 = __fmul_rn(kp[2], 2048.0f), kx1 = __fmul_rn(kp[3], 2048.0f);
        float ky2 = __fmul_rn(kp[4], 2048.0f), kx2 = __fmul_rn(kp[5], 2048.0f);
        float py = __fadd_rn(__fadd_rn(__fmul_rn(b0, ky0), __fmul_rn(b1, ky1)),
                             __fmul_rn(b2, ky2));
        float px = __fadd_rn(__fadd_rn(__fmul_rn(b0, kx0), __fmul_rn(b1, kx1)),
                             __fmul_rn(b2, kx2));
        // Exact point-to-tile-box distance; squared threshold 4.5 (> 4.0) pads
        // against rounding — only ever KEEPS extra samples, never drops one.
        float bdy = fmaxf(fmaxf((float)y0 - py, py - (float)(y0 + TILE_H - 1)), 0.0f);
        float bdx = fmaxf(fmaxf((float)x0 - px, px - (float)(x0 + TILE_W - 1)), 0.0f);
        bool near = (bdy * bdy + bdx * bdx) < 4.5f;
        unsigned mask = __ballot_sync(0xffffffffu, near);
        if (near) {
            int idx = __popc(mask & ((1u << tx) - 1u));
            csy[idx] = py;
            csx[idx] = px;
        }
        if (tx == 0) s_count = __popc(mask);
    }
    __syncthreads();

    const int cnt = s_count;
    const int x = x0 + tx * 4;
    float* row0 = out + (size_t)(y0 + ty) * CANVAS_W + x;

    if (cnt == 0) {
        const float4 z = make_float4(0.0f, 0.0f, 0.0f, 0.0f);
        #pragma unroll
        for (int r = 0; r < 4; r++)
            *reinterpret_cast<float4*>(row0 + (size_t)r * 8 * CANVAS_W) = z;
    } else {
        const float maxd = sqrtf(2048.0f * 2048.0f + 2048.0f * 2048.0f);
        const float fx0 = (float)x;
        const float fx1 = fx0 + 1.0f;
        const float fx2 = fx0 + 2.0f;
        const float fx3 = fx0 + 3.0f;
        #pragma unroll
        for (int r = 0; r < 4; r++) {
            const float fy = (float)(y0 + ty + r * 8);
            float m0 = 3.4e38f, m1 = 3.4e38f, m2 = 3.4e38f, m3 = 3.4e38f;
            for (int s = 0; s < cnt; s++) {
                float syv = csy[s];
                float sxv = csx[s];
                float dy  = __fsub_rn(fy, syv);
                float dy2 = __fmul_rn(dy, dy);     // separate op, matches ref
                float d;
                d = __fsub_rn(fx0, sxv); m0 = fminf(m0, __fadd_rn(dy2, __fmul_rn(d, d)));
                d = __fsub_rn(fx1, sxv); m1 = fminf(m1, __fadd_rn(dy2, __fmul_rn(d, d)));
                d = __fsub_rn(fx2, sxv); m2 = fminf(m2, __fadd_rn(dy2, __fmul_rn(d, d)));
                d = __fsub_rn(fx3, sxv); m3 = fminf(m3, __fadd_rn(dy2, __fmul_rn(d, d)));
            }
            // sqrt BEFORE compare (boundary rounding identical to reference)
            float d0 = sqrtf(m0), d1 = sqrtf(m1), d2s = sqrtf(m2), d3 = sqrtf(m3);
            float4 v;
            v.x = (d0  < 2.0f) ? __fsub_rn(1.0f, __fdiv_rn(d0,  maxd)) : 0.0f;
            v.y = (d1  < 2.0f) ? __fsub_rn(1.0f, __fdiv_rn(d1,  maxd)) : 0.0f;
            v.z = (d2s < 2.0f) ? __fsub_rn(1.0f, __fdiv_rn(d2s, maxd)) : 0.0f;
            v.w = (d3  < 2.0f) ? __fsub_rn(1.0f, __fdiv_rn(d3,  maxd)) : 0.0f;
            *reinterpret_cast<float4*>(row0 + (size_t)r * 8 * CANVAS_W) = v;
        }
    }
}

extern "C" void kernel_launch(void* const* d_in, const int* in_sizes, int n_in,
                              void* d_out, int out_size)
{
    const float* kp = (const float*)d_in[0];   // [3,2] normalized (y,x)
    float* out = (float*)d_out;                // [2048,2048] fp32

    dim3 block(32, 8);
    dim3 grid(CANVAS_W / TILE_W, CANVAS_H / TILE_H);  // (16, 64) = 1024 blocks
    path_raster_kernel<<<grid, block>>>(kp, out);
}

// round 3
// speedup vs baseline: 1.0257x; 1.0257x over previous
#include <cuda_runtime.h>
#include <cuda_bf16.h>

// PathRaster2d: quadratic Bezier (3 cps) on 2048x2048.
// R3: warp-autonomous. No shared mem, no __syncthreads. Each warp computes the
// 32 curve samples (one per lane), exact point-to-box prune vs its 128x64 tile,
// ballot; zero tiles issue 8 straight STG.128. Active warps (rare) gather near
// samples via shfl. Arithmetic bit-identical to R2 (rel_err was 0.0).

#define CANVAS_H 2048
#define CANVAS_W 2048
#define TILE_W 128
#define TILE_H 64
#define ROWS_PER_THREAD 8
#define ROW_STRIDE 8            // ty in [0,8), rows ty + 8r

__global__ void __launch_bounds__(256)
path_raster_kernel(const float* __restrict__ kp, float* __restrict__ out)
{
    const int tx = threadIdx.x;          // 0..31 (lane == sample index)
    const int ty = threadIdx.y;          // 0..7
    const int x0 = blockIdx.x * TILE_W;
    const int y0 = blockIdx.y * TILE_H;

    // ---- per-lane sample (lane i computes sample i), ref-matched rounding ----
    // t_i = i * fl(1/31), endpoint forced to 1.0 (matches jnp.linspace)
    float t = (tx == 31) ? 1.0f : (float)tx * (1.0f / 31.0f);
    float u = __fsub_rn(1.0f, t);
    float b0 = __fmul_rn(u, u);
    float b1 = __fmul_rn(__fmul_rn(2.0f, t), u);
    float b2 = __fmul_rn(t, t);
    float ky0 = __fmul_rn(__ldg(kp + 0), 2048.0f), kx0 = __fmul_rn(__ldg(kp + 1), 2048.0f);
    float ky1 = __fmul_rn(__ldg(kp + 2), 2048.0f), kx1 = __fmul_rn(__ldg(kp + 3), 2048.0f);
    float ky2 = __fmul_rn(__ldg(kp + 4), 2048.0f), kx2 = __fmul_rn(__ldg(kp + 5), 2048.0f);
    float py = __fadd_rn(__fadd_rn(__fmul_rn(b0, ky0), __fmul_rn(b1, ky1)),
                         __fmul_rn(b2, ky2));
    float px = __fadd_rn(__fadd_rn(__fmul_rn(b0, kx0), __fmul_rn(b1, kx1)),
                         __fmul_rn(b2, kx2));

    // Exact point-to-tile-box distance. Squared threshold 4.5 (> 4.0) pads for
    // rounding — only ever KEEPS extra samples (dist(pixel,s) >= boxdist(s)).
    float bdy = fmaxf(fmaxf((float)y0 - py, py - (float)(y0 + TILE_H - 1)), 0.0f);
    float bdx = fmaxf(fmaxf((float)x0 - px, px - (float)(x0 + TILE_W - 1)), 0.0f);
    bool near = (bdy * bdy + bdx * bdx) < 4.5f;
    unsigned mask = __ballot_sync(0xffffffffu, near);

    const int x = x0 + tx * 4;
    float* base = out + (size_t)(y0 + ty) * CANVAS_W + x;

    if (mask == 0u) {
        const float4 z = make_float4(0.0f, 0.0f, 0.0f, 0.0f);
        #pragma unroll
        for (int r = 0; r < ROWS_PER_THREAD; r++)
            *reinterpret_cast<float4*>(base + (size_t)(r * ROW_STRIDE) * CANVAS_W) = z;
    } else {
        const float maxd = sqrtf(2048.0f * 2048.0f + 2048.0f * 2048.0f);
        const float fx0 = (float)x;
        const float fx1 = fx0 + 1.0f;
        const float fx2 = fx0 + 2.0f;
        const float fx3 = fx0 + 3.0f;
        #pragma unroll
        for (int r = 0; r < ROWS_PER_THREAD; r++) {
            const float fy = (float)(y0 + ty + r * ROW_STRIDE);
            float m0 = 3.4e38f, m1 = 3.4e38f, m2 = 3.4e38f, m3 = 3.4e38f;
            unsigned mm = mask;              // warp-uniform -> uniform loop
            while (mm) {
                int lane = __ffs(mm) - 1;
                mm &= mm - 1u;
                float syv = __shfl_sync(0xffffffffu, py, lane);
                float sxv = __shfl_sync(0xffffffffu, px, lane);
                float dy  = __fsub_rn(fy, syv);
                float dy2 = __fmul_rn(dy, dy);   // separate op, matches ref
                float d;
                d = __fsub_rn(fx0, sxv); m0 = fminf(m0, __fadd_rn(dy2, __fmul_rn(d, d)));
                d = __fsub_rn(fx1, sxv); m1 = fminf(m1, __fadd_rn(dy2, __fmul_rn(d, d)));
                d = __fsub_rn(fx2, sxv); m2 = fminf(m2, __fadd_rn(dy2, __fmul_rn(d, d)));
                d = __fsub_rn(fx3, sxv); m3 = fminf(m3, __fadd_rn(dy2, __fmul_rn(d, d)));
            }
            // sqrt BEFORE compare (boundary rounding identical to reference)
            float d0 = sqrtf(m0), d1 = sqrtf(m1), d2s = sqrtf(m2), d3 = sqrtf(m3);
            float4 v;
            v.x = (d0  < 2.0f) ? __fsub_rn(1.0f, __fdiv_rn(d0,  maxd)) : 0.0f;
            v.y = (d1  < 2.0f) ? __fsub_rn(1.0f, __fdiv_rn(d1,  maxd)) : 0.0f;
            v.z = (d2s < 2.0f) ? __fsub_rn(1.0f, __fdiv_rn(d2s, maxd)) : 0.0f;
            v.w = (d3  < 2.0f) ? __fsub_rn(1.0f, __fdiv_rn(d3,  maxd)) : 0.0f;
            *reinterpret_cast<float4*>(base + (size_t)(r * ROW_STRIDE) * CANVAS_W) = v;
        }
    }
}

extern "C" void kernel_launch(void* const* d_in, const int* in_sizes, int n_in,
                              void* d_out, int out_size)
{
    const float* kp = (const float*)d_in[0];   // [3,2] normalized (y,x)
    float* out = (float*)d_out;                // [2048,2048] fp32

    dim3 block(32, 8);
    dim3 grid(CANVAS_W / TILE_W, CANVAS_H / TILE_H);  // (16, 32) = 512 blocks
    path_raster_kernel<<<grid, block>>>(kp, out);
}